// round 9
// baseline (speedup 1.0000x reference)
#include <cuda_runtime.h>

// NTM forward: B=2048, T=64, I=9, N=128, V=20, S=3, C=100, O=8
#define TT 64
#define II 9
#define NN 128
#define VV 20
#define CC 100
#define OO 8
#define MP 22               // M row pitch (float2-friendly, conflict-free)
#define EPSF 1e-8f

#define NGROUPS 8
#define GTHREADS 64

// smem layout (floats)
#define WCT_OFF   0        // 100 x 36  (Wc^T rows, cols 29..35 zero)
#define WHT_OFF   3600     // 92 x 104  (head W^T rows: o<26 Wr col o else Ww col o-26; cols 100..103 zero)
#define WF_OFF    13168    // 120 x 8
#define BC_OFF    14128    // 100
#define BH_OFF    14228    // 92 (br | bw)
#define BF_OFF    14320    // 8
#define HALL_OFF  14328    // 104 x 8  h_all[c][g], rows 100..103 zero
#define CALL_OFF  15160    // 36 x 8   cat_all[i][g], rows 29..35 zero
#define CHALF_OFF 15448    // 92 x 8   C-phase half-1 partials
#define GS_OFF    16184

struct GroupState {
    float Ms[NN * MP];          // 2816
    float kr[VV], kw[VV], ev[VV], av[VV];   // 80
    float wprev[NN], wr[NN], wg[NN];        // 384
    float part[80];
    float redA[2], redB[2];
    float scal[12];             // beta_r,g_r,gamma_r,s_r(3), beta_w,g_w,gamma_w,s_w(3)
    float praw[6];
    float knorm[2];
    float pad_[12];             // size 3396 floats == 4 (mod 32) -> conflict-free group stride
};

#define DYN_SMEM_BYTES ((GS_OFF + NGROUPS * (int)(sizeof(GroupState) / 4)) * 4)

__device__ __forceinline__ float sigmoidf_(float x) {
    return 1.0f / (1.0f + __expf(-x));
}
__device__ __forceinline__ float softplusf_(float x) {
    return fmaxf(x, 0.0f) + log1pf(__expf(-fabsf(x)));
}
__device__ __forceinline__ float ex2_(float x) {
    float r;
    asm("ex2.approx.ftz.f32 %0, %1;" : "=f"(r) : "f"(x));
    return r;
}
__device__ __forceinline__ void gbar(int g) {   // 64-thread group barrier (ids 1..8)
    asm volatile("bar.sync %0, 64;" :: "r"(g + 1) : "memory");
}
// acc[0..7] += w * act_all[i][0..7], act rows interleaved by 8
__device__ __forceinline__ void fma8(float* acc, float w, const float4* b4, int i) {
    float4 a = b4[2 * i], b = b4[2 * i + 1];
    acc[0] = fmaf(w, a.x, acc[0]); acc[1] = fmaf(w, a.y, acc[1]);
    acc[2] = fmaf(w, a.z, acc[2]); acc[3] = fmaf(w, a.w, acc[3]);
    acc[4] = fmaf(w, b.x, acc[4]); acc[5] = fmaf(w, b.y, acc[5]);
    acc[6] = fmaf(w, b.z, acc[6]); acc[7] = fmaf(w, b.w, acc[7]);
}

__global__ __launch_bounds__(512, 1) void ntm_kernel(
    const float* __restrict__ x,
    const float* __restrict__ Wc, const float* __restrict__ bc,
    const float* __restrict__ Wr, const float* __restrict__ br,
    const float* __restrict__ Ww, const float* __restrict__ bw,
    const float* __restrict__ Wf, const float* __restrict__ bf,
    const float* __restrict__ r_bias, const float* __restrict__ M_bias,
    float* __restrict__ out, int Btot)
{
    extern __shared__ float sm[];
    const int tid = threadIdx.x;

    // ---- one-time weight staging (transposed) ----
    for (int i = tid; i < 3600; i += 512) sm[WCT_OFF + i] = 0.0f;
    for (int i = tid; i < 9568; i += 512) sm[WHT_OFF + i] = 0.0f;
    for (int i = tid; i < 832;  i += 512) sm[HALL_OFF + i] = 0.0f;
    for (int i = tid; i < 288;  i += 512) sm[CALL_OFF + i] = 0.0f;
    __syncthreads();
    for (int i = tid; i < 2900; i += 512) {          // WcT[o][i] = Wc[i*100+o]
        int r = i / 100, c = i % 100;
        sm[WCT_OFF + c * 36 + r] = Wc[i];
    }
    for (int i = tid; i < 2600; i += 512) {          // rows 0..25 from Wr
        int c = i / 26, o = i % 26;
        sm[WHT_OFF + o * 104 + c] = Wr[i];
    }
    for (int i = tid; i < 6600; i += 512) {          // rows 26..91 from Ww
        int c = i / 66, o = i % 66;
        sm[WHT_OFF + (26 + o) * 104 + c] = Ww[i];
    }
    for (int i = tid; i < 960;  i += 512) sm[WF_OFF + i] = Wf[i];
    for (int i = tid; i < 100;  i += 512) sm[BC_OFF + i] = bc[i];
    for (int i = tid; i < 26;   i += 512) sm[BH_OFF + i] = br[i];
    for (int i = tid; i < 66;   i += 512) sm[BH_OFF + 26 + i] = bw[i];
    for (int i = tid; i < 8;    i += 512) sm[BF_OFF + i] = bf[i];
    __syncthreads();

    const int group = tid >> 6;           // 0..7
    const int gtid = tid & 63;            // 0..63
    const int lane = tid & 31;
    const int gw = gtid >> 5;             // warp within group: 0/1
    GroupState* gsArr = reinterpret_cast<GroupState*>(sm + GS_OFF);
    GroupState* gs = gsArr + group;

    const float* Wfs = sm + WF_OFF;
    const float* bfs = sm + BF_OFF;
    const int r0 = gtid, r1 = gtid + 64;

    for (int bb = blockIdx.x * NGROUPS; bb < Btot; bb += gridDim.x * NGROUPS) {
        const int b = bb + group;
        const bool active = (b < Btot);
        const float* xb = active ? (x + (size_t)b * TT * II) : x;
        float* ob = active ? (out + (size_t)b * TT * OO) : out;

        // ---- per-batch state init ----
        for (int idx = gtid; idx < NN * VV; idx += GTHREADS)
            gs->Ms[(idx / VV) * MP + (idx % VV)] = M_bias[idx];
        if (gtid < VV) sm[CALL_OFF + (II + gtid) * 8 + group] = r_bias[gtid];
        gs->wprev[r0] = 0.0f; gs->wprev[r1] = 0.0f;
        if (gtid < II) sm[CALL_OFF + gtid * 8 + group] = xb[gtid];
        __syncthreads();

        for (int t = 0; t < TT; ++t) {
            // ---- B: controller for all 8 groups (threads 0..99) ----
            if (tid < CC) {
                const float4* w4 = reinterpret_cast<const float4*>(sm + WCT_OFF + tid * 36);
                const float4* c4 = reinterpret_cast<const float4*>(sm + CALL_OFF);
                float acc[8];
                float b0 = sm[BC_OFF + tid];
                #pragma unroll
                for (int g = 0; g < 8; ++g) acc[g] = b0;
                #pragma unroll
                for (int k = 0; k < 9; ++k) {     // i = 0..35 (pads are zero)
                    float4 wv = w4[k];
                    fma8(acc, wv.x, c4, 4 * k + 0);
                    fma8(acc, wv.y, c4, 4 * k + 1);
                    fma8(acc, wv.z, c4, 4 * k + 2);
                    fma8(acc, wv.w, c4, 4 * k + 3);
                }
                float4* h4o = reinterpret_cast<float4*>(sm + HALL_OFF + tid * 8);
                h4o[0] = make_float4(tanhf(acc[0]), tanhf(acc[1]), tanhf(acc[2]), tanhf(acc[3]));
                h4o[1] = make_float4(tanhf(acc[4]), tanhf(acc[5]), tanhf(acc[6]), tanhf(acc[7]));
            }
            __syncthreads();

            // ---- C: head GEMM for all 8 groups (threads 0..183, split c-halves) ----
            float cacc[8];
            const int co = (tid < 184) ? (tid % 92) : 0;
            const int ch = (tid < 184) ? (tid / 92) : 0;
            if (tid < 184) {
                const float4* w4 = reinterpret_cast<const float4*>(sm + WHT_OFF + co * 104 + ch * 52);
                const float4* h4 = reinterpret_cast<const float4*>(sm + HALL_OFF);
                float b0 = ch ? 0.0f : sm[BH_OFF + co];
                #pragma unroll
                for (int g = 0; g < 8; ++g) cacc[g] = b0;
                const int cb = ch * 52;
                #pragma unroll
                for (int k = 0; k < 13; ++k) {    // c = cb..cb+51 (pads zero)
                    float4 wv = w4[k];
                    fma8(cacc, wv.x, h4, cb + 4 * k + 0);
                    fma8(cacc, wv.y, h4, cb + 4 * k + 1);
                    fma8(cacc, wv.z, h4, cb + 4 * k + 2);
                    fma8(cacc, wv.w, h4, cb + 4 * k + 3);
                }
                if (ch) {
                    float4* s4 = reinterpret_cast<float4*>(sm + CHALF_OFF + co * 8);
                    s4[0] = make_float4(cacc[0], cacc[1], cacc[2], cacc[3]);
                    s4[1] = make_float4(cacc[4], cacc[5], cacc[6], cacc[7]);
                }
            }
            __syncthreads();
            if (tid < 92) {                        // combine + activation dispatch
                const float* chp = sm + CHALF_OFF + tid * 8;
                const int o = tid;
                #pragma unroll
                for (int g = 0; g < 8; ++g) {
                    GroupState* G = gsArr + g;
                    float v = cacc[g] + chp[g];
                    if (o < 20)       G->kr[o] = tanhf(v);
                    else if (o == 20) G->scal[0] = softplusf_(v);
                    else if (o == 21) G->scal[1] = sigmoidf_(v);
                    else if (o < 25)  G->praw[o - 22] = v;
                    else if (o == 25) G->scal[2] = 1.0f + softplusf_(v);
                    else if (o < 46)  G->kw[o - 26] = tanhf(v);
                    else if (o == 46) G->scal[6] = softplusf_(v);
                    else if (o == 47) G->scal[7] = sigmoidf_(v);
                    else if (o < 51)  G->praw[3 + o - 48] = v;
                    else if (o == 51) G->scal[8] = 1.0f + softplusf_(v);
                    else if (o < 72)  G->ev[o - 52] = sigmoidf_(v);
                    else              G->av[o - 72] = tanhf(v);
                }
            }
            __syncthreads();

            // ---- D: fused pass over M (2 rows/thread, float2) + side jobs ----
            float dr0 = 0.0f, dw0 = 0.0f, ss0 = 0.0f;
            float dr1 = 0.0f, dw1 = 0.0f, ss1 = 0.0f;
            {
                const float2* M0 = reinterpret_cast<const float2*>(&gs->Ms[r0 * MP]);
                const float2* M1 = reinterpret_cast<const float2*>(&gs->Ms[r1 * MP]);
                const float2* kr2 = reinterpret_cast<const float2*>(gs->kr);
                const float2* kw2 = reinterpret_cast<const float2*>(gs->kw);
                #pragma unroll
                for (int v = 0; v < VV / 2; ++v) {
                    float2 kvr = kr2[v], kvw = kw2[v];
                    float2 m0 = M0[v], m1 = M1[v];
                    dr0 = fmaf(m0.x, kvr.x, dr0); dr0 = fmaf(m0.y, kvr.y, dr0);
                    dw0 = fmaf(m0.x, kvw.x, dw0); dw0 = fmaf(m0.y, kvw.y, dw0);
                    ss0 = fmaf(m0.x, m0.x, ss0);  ss0 = fmaf(m0.y, m0.y, ss0);
                    dr1 = fmaf(m1.x, kvr.x, dr1); dr1 = fmaf(m1.y, kvr.y, dr1);
                    dw1 = fmaf(m1.x, kvw.x, dw1); dw1 = fmaf(m1.y, kvw.y, dw1);
                    ss1 = fmaf(m1.x, m1.x, ss1);  ss1 = fmaf(m1.y, m1.y, ss1);
                }
            }
            const float mn0 = sqrtf(ss0), mn1 = sqrtf(ss1);
            if (gtid == 40) {                      // s_r softmax(3)
                float a0 = gs->praw[0], a1 = gs->praw[1], a2 = gs->praw[2];
                float m = fmaxf(a0, fmaxf(a1, a2));
                float e0 = __expf(a0 - m), e1 = __expf(a1 - m), e2 = __expf(a2 - m);
                float s = e0 + e1 + e2;
                gs->scal[3] = e0 / s; gs->scal[4] = e1 / s; gs->scal[5] = e2 / s;
            } else if (gtid == 41) {               // |kr|
                float s2 = 0.0f;
                #pragma unroll
                for (int v = 0; v < VV; ++v) s2 = fmaf(gs->kr[v], gs->kr[v], s2);
                gs->knorm[0] = sqrtf(s2);
            } else if (gtid == 42) {               // s_w softmax(3)
                float a0 = gs->praw[3], a1 = gs->praw[4], a2 = gs->praw[5];
                float m = fmaxf(a0, fmaxf(a1, a2));
                float e0 = __expf(a0 - m), e1 = __expf(a1 - m), e2 = __expf(a2 - m);
                float s = e0 + e1 + e2;
                gs->scal[9] = e0 / s; gs->scal[10] = e1 / s; gs->scal[11] = e2 / s;
            } else if (gtid == 43) {               // |kw|
                float s2 = 0.0f;
                #pragma unroll
                for (int v = 0; v < VV; ++v) s2 = fmaf(gs->kw[v], gs->kw[v], s2);
                gs->knorm[1] = sqrtf(s2);
            }
            gbar(group);

            // ---- E: dual-head content softmax (no max pass; |z| small) ----
            const float g_r = gs->scal[1], gamma_r = gs->scal[2];
            const float s0r = gs->scal[3], s1r = gs->scal[4], s2r = gs->scal[5];
            const float g_w = gs->scal[7], gamma_w = gs->scal[8];
            const float s0w = gs->scal[9], s1w = gs->scal[10], s2w = gs->scal[11];
            const float beta_r = gs->scal[0], beta_w = gs->scal[6];
            const float knr = gs->knorm[0], knw = gs->knorm[1];
            float er0 = __expf(beta_r * __fdividef(dr0, fmaf(knr, mn0, EPSF)));
            float er1 = __expf(beta_r * __fdividef(dr1, fmaf(knr, mn1, EPSF)));
            float ew0 = __expf(beta_w * __fdividef(dw0, fmaf(knw, mn0, EPSF)));
            float ew1 = __expf(beta_w * __fdividef(dw1, fmaf(knw, mn1, EPSF)));
            float sr = er0 + er1, sw = ew0 + ew1;
            #pragma unroll
            for (int o = 16; o; o >>= 1) {
                sr += __shfl_xor_sync(0xffffffffu, sr, o);
                sw += __shfl_xor_sync(0xffffffffu, sw, o);
            }
            if (lane == 0) { gs->redA[gw] = sr; gs->redB[gw] = sw; }
            gbar(group);
            {
                float isr = __fdividef(1.0f, gs->redA[0] + gs->redA[1]);
                float isw = __fdividef(1.0f, gs->redB[0] + gs->redB[1]);
                float wcr0 = er0 * isr, wcr1 = er1 * isr;
                gs->wg[r0] = fmaf(g_r, wcr0 - gs->wprev[r0], gs->wprev[r0]);
                gs->wg[r1] = fmaf(g_r, wcr1 - gs->wprev[r1], gs->wprev[r1]);
                er0 = ew0 * isw; er1 = ew1 * isw;    // stash wcw0, wcw1
            }
            gbar(group);

            // ---- F: read-head shift + sharpen ----
            {
                float ws0 = s0r * gs->wg[(r0 + 1) & (NN - 1)] + s1r * gs->wg[r0]
                          + s2r * gs->wg[(r0 + NN - 1) & (NN - 1)];
                float ws1 = s0r * gs->wg[(r1 + 1) & (NN - 1)] + s1r * gs->wg[r1]
                          + s2r * gs->wg[(r1 + NN - 1) & (NN - 1)];
                float wp0 = (ws0 > 0.0f) ? ex2_(gamma_r * __log2f(ws0)) : 0.0f;
                float wp1 = (ws1 > 0.0f) ? ex2_(gamma_r * __log2f(ws1)) : 0.0f;
                float sp = wp0 + wp1;
                #pragma unroll
                for (int o = 16; o; o >>= 1) sp += __shfl_xor_sync(0xffffffffu, sp, o);
                if (lane == 0) gs->redA[gw] = sp;
                gbar(group);
                float isp = __fdividef(1.0f, gs->redA[0] + gs->redA[1] + EPSF);
                gs->wr[r0] = wp0 * isp;
                gs->wr[r1] = wp1 * isp;
            }
            gbar(group);

            // ---- G: write-head interpolation || r = wr @ M (60 thr) ----
            gs->wg[r0] = fmaf(g_w, er0 - gs->wr[r0], gs->wr[r0]);
            gs->wg[r1] = fmaf(g_w, er1 - gs->wr[r1], gs->wr[r1]);
            if (gtid < 60) {
                const int v = gtid % 20, q = gtid / 20;
                const int beg = q * 43, end = (q == 2) ? NN : beg + 43;
                float acc = 0.0f;
                for (int j = beg; j < end; ++j)
                    acc = fmaf(gs->wr[j], gs->Ms[j * MP + v], acc);
                gs->part[q * 20 + v] = acc;
            }
            gbar(group);

            // ---- H: write-head shift + sharpen || r combine -> cat_all ----
            float wpw0, wpw1;
            {
                float ws0 = s0w * gs->wg[(r0 + 1) & (NN - 1)] + s1w * gs->wg[r0]
                          + s2w * gs->wg[(r0 + NN - 1) & (NN - 1)];
                float ws1 = s0w * gs->wg[(r1 + 1) & (NN - 1)] + s1w * gs->wg[r1]
                          + s2w * gs->wg[(r1 + NN - 1) & (NN - 1)];
                wpw0 = (ws0 > 0.0f) ? ex2_(gamma_w * __log2f(ws0)) : 0.0f;
                wpw1 = (ws1 > 0.0f) ? ex2_(gamma_w * __log2f(ws1)) : 0.0f;
                float sp = wpw0 + wpw1;
                #pragma unroll
                for (int o = 16; o; o >>= 1) sp += __shfl_xor_sync(0xffffffffu, sp, o);
                if (lane == 0) gs->redB[gw] = sp;
            }
            if (gtid < VV)
                sm[CALL_OFF + (II + gtid) * 8 + group] =
                    gs->part[gtid] + gs->part[20 + gtid] + gs->part[40 + gtid];
            gbar(group);

            // ---- I: finalize ww + M update || output partials ----
            {
                float isp = __fdividef(1.0f, gs->redB[0] + gs->redB[1] + EPSF);
                float ww0 = wpw0 * isp, ww1 = wpw1 * isp;
                gs->wprev[r0] = ww0; gs->wprev[r1] = ww1;
                float2* M0 = reinterpret_cast<float2*>(&gs->Ms[r0 * MP]);
                float2* M1 = reinterpret_cast<float2*>(&gs->Ms[r1 * MP]);
                const float2* ev2 = reinterpret_cast<const float2*>(gs->ev);
                const float2* av2 = reinterpret_cast<const float2*>(gs->av);
                #pragma unroll
                for (int v = 0; v < VV / 2; ++v) {
                    float2 e = ev2[v], a = av2[v];
                    float2 m0 = M0[v], m1 = M1[v];
                    m0.x = fmaf(ww0, a.x - e.x * m0.x, m0.x);
                    m0.y = fmaf(ww0, a.y - e.y * m0.y, m0.y);
                    m1.x = fmaf(ww1, a.x - e.x * m1.x, m1.x);
                    m1.y = fmaf(ww1, a.y - e.y * m1.y, m1.y);
                    M0[v] = m0; M1[v] = m1;
                }
            }
            {
                const int o = gtid & 7, seg = gtid >> 3;      // 8 segs of 15
                float acc = 0.0f;
                #pragma unroll
                for (int j = seg * 15; j < seg * 15 + 15; ++j) {
                    float v = (j < CC) ? sm[HALL_OFF + j * 8 + group]
                                       : sm[CALL_OFF + (II + (j - CC)) * 8 + group];
                    acc = fmaf(v, Wfs[j * 8 + o], acc);
                }
                gs->part[gtid] = acc;
            }
            gbar(group);

            // ---- J: output store || prefetch x_{t+1} ----
            if (active && gtid < OO) {
                float s = bfs[gtid];
                #pragma unroll
                for (int q = 0; q < 8; ++q) s += gs->part[q * 8 + gtid];
                ob[t * OO + gtid] = sigmoidf_(s);
            }
            if (active && gtid >= 40 && gtid < 40 + II && t + 1 < TT)
                sm[CALL_OFF + (gtid - 40) * 8 + group] = xb[(t + 1) * II + (gtid - 40)];
            __syncthreads();   // step boundary: all groups' cat/h consistent for B
        }
    }
}

extern "C" void kernel_launch(void* const* d_in, const int* in_sizes, int n_in,
                              void* d_out, int out_size) {
    const float* x      = (const float*)d_in[0];
    const float* Wc     = (const float*)d_in[1];
    const float* bc     = (const float*)d_in[2];
    const float* Wr     = (const float*)d_in[3];
    const float* br     = (const float*)d_in[4];
    const float* Ww     = (const float*)d_in[5];
    const float* bw     = (const float*)d_in[6];
    const float* Wf     = (const float*)d_in[7];
    const float* bf     = (const float*)d_in[8];
    const float* r_bias = (const float*)d_in[9];
    const float* M_bias = (const float*)d_in[10];
    float* out = (float*)d_out;

    const int Btot = in_sizes[0] / (TT * II);
    cudaFuncSetAttribute(ntm_kernel, cudaFuncAttributeMaxDynamicSharedMemorySize,
                         DYN_SMEM_BYTES);
    int grid = (Btot + NGROUPS - 1) / NGROUPS;
    if (grid < 1) grid = 1;
    ntm_kernel<<<grid, 512, DYN_SMEM_BYTES>>>(x, Wc, bc, Wr, br, Ww, bw, Wf, bf,
                                              r_bias, M_bias, out, Btot);
}

// round 11
// speedup vs baseline: 1.8691x; 1.8691x over previous
#include <cuda_runtime.h>

// NTM forward: B=2048, T=64, I=9, N=128, V=20, S=3, C=100, O=8
#define TT 64
#define II 9
#define NN 128
#define VV 20
#define CC 100
#define OO 8
#define EPSF 1e-8f

#define NGROUPS 7
#define GTHREADS 64
#define NB_PER_CTA (NGROUPS * 2)

// smem weight layout (floats)
#define WCT_OFF 0            // 100 x 36 (Wc^T rows; cols 29..35 zero)
#define WHT_OFF 3600         // 92 x 100 (head rows: o<26 -> Wr col o, else Ww col o-26)
#define WF_OFF  12800        // 120 x 8
#define BC_OFF  13760        // 100
#define BH_OFF  13860        // 92 (br | bw)
#define BF_OFF  13952        // 8
#define GS_OFF  13960        // 16B aligned (13960*4 % 16 == 0)

struct GroupState {
    float Ms[2][NN * VV];        // 5120 (float4 rows, stride 20 conflict-free)
    float h[2][104];             // 208 (100 used)
    float cat[2][36];            // 72  (x(9), r(20), zero pad 29..35)
    float kr[2][VV], kw[2][VV], ev[2][VV], av[2][VV];   // 160
    float wprev[2][NN];          // 256
    float wr[NN], wg[NN];        // 256 (shared transient, one lb at a time)
    float part[80];
    float redA[2], redB[2];
    float scal[2][12];
    float praw[2][6];
    float knorm[2][2];
};                                // 6196 floats = 24784 B

#define DYN_SMEM_BYTES ((GS_OFF + NGROUPS * (int)(sizeof(GroupState) / 4)) * 4)

__device__ __forceinline__ float sigmoidf_(float x) {
    return 1.0f / (1.0f + __expf(-x));
}
__device__ __forceinline__ float softplusf_(float x) {
    return fmaxf(x, 0.0f) + log1pf(__expf(-fabsf(x)));
}
__device__ __forceinline__ float ex2_(float x) {
    float r;
    asm("ex2.approx.ftz.f32 %0, %1;" : "=f"(r) : "f"(x));
    return r;
}
__device__ __forceinline__ void gbar(int g) {   // 64-thread group barrier (ids 1..7)
    asm volatile("bar.sync %0, 64;" :: "r"(g + 1) : "memory");
}
__device__ __forceinline__ float dot4(const float4 a, const float4 b, float acc) {
    acc = fmaf(a.x, b.x, acc); acc = fmaf(a.y, b.y, acc);
    acc = fmaf(a.z, b.z, acc); acc = fmaf(a.w, b.w, acc);
    return acc;
}

__device__ __forceinline__ void head_dispatch(GroupState* G, int lb, int o, float v) {
    if (o < 20)       G->kr[lb][o] = tanhf(v);
    else if (o == 20) G->scal[lb][0] = softplusf_(v);
    else if (o == 21) G->scal[lb][1] = sigmoidf_(v);
    else if (o < 25)  G->praw[lb][o - 22] = v;
    else if (o == 25) G->scal[lb][2] = 1.0f + softplusf_(v);
    else if (o < 46)  G->kw[lb][o - 26] = tanhf(v);
    else if (o == 46) G->scal[lb][6] = softplusf_(v);
    else if (o == 47) G->scal[lb][7] = sigmoidf_(v);
    else if (o < 51)  G->praw[lb][3 + o - 48] = v;
    else if (o == 51) G->scal[lb][8] = 1.0f + softplusf_(v);
    else if (o < 72)  G->ev[lb][o - 52] = sigmoidf_(v);
    else              G->av[lb][o - 72] = tanhf(v);
}

__global__ __launch_bounds__(448, 1) void ntm_kernel(
    const float* __restrict__ x,
    const float* __restrict__ Wc, const float* __restrict__ bc,
    const float* __restrict__ Wr, const float* __restrict__ br,
    const float* __restrict__ Ww, const float* __restrict__ bw,
    const float* __restrict__ Wf, const float* __restrict__ bf,
    const float* __restrict__ r_bias, const float* __restrict__ M_bias,
    float* __restrict__ out, int Btot)
{
    extern __shared__ float sm[];
    const int tid = threadIdx.x;

    // ---- one-time transposed weight staging ----
    for (int i = tid; i < 3600; i += 448) sm[WCT_OFF + i] = 0.0f;
    __syncthreads();
    for (int i = tid; i < 2900; i += 448) {          // WcT[o][i] = Wc[i*100+o]
        int r = i / 100, c = i % 100;
        sm[WCT_OFF + c * 36 + r] = Wc[i];
    }
    for (int i = tid; i < 2600; i += 448) {          // rows 0..25 from Wr
        int c = i / 26, o = i % 26;
        sm[WHT_OFF + o * 100 + c] = Wr[i];
    }
    for (int i = tid; i < 6600; i += 448) {          // rows 26..91 from Ww
        int c = i / 66, o = i % 66;
        sm[WHT_OFF + (26 + o) * 100 + c] = Ww[i];
    }
    for (int i = tid; i < 960;  i += 448) sm[WF_OFF + i] = Wf[i];
    for (int i = tid; i < 100;  i += 448) sm[BC_OFF + i] = bc[i];
    for (int i = tid; i < 26;   i += 448) sm[BH_OFF + i] = br[i];
    for (int i = tid; i < 66;   i += 448) sm[BH_OFF + 26 + i] = bw[i];
    for (int i = tid; i < 8;    i += 448) sm[BF_OFF + i] = bf[i];
    __syncthreads();

    const int group = tid >> 6;           // 0..6
    const int gtid = tid & 63;            // 0..63
    const int lane = tid & 31;
    const int gw = gtid >> 5;             // warp within group: 0/1
    GroupState* gs = reinterpret_cast<GroupState*>(sm + GS_OFF) + group;

    const float* Wfs = sm + WF_OFF;
    const float* bfs = sm + BF_OFF;
    const int r0 = gtid, r1 = gtid + 64;

    const int base = (blockIdx.x * NGROUPS + group) * 2;
    const int b0e = (base < Btot) ? base : (Btot - 1);          // clamped for safe loads
    const int b1e = (base + 1 < Btot) ? (base + 1) : (Btot - 1);
    const bool act0 = (base < Btot), act1 = (base + 1 < Btot);
    const float* xb[2] = { x + (size_t)b0e * TT * II, x + (size_t)b1e * TT * II };
    float* ob[2] = { out + (size_t)b0e * TT * OO, out + (size_t)b1e * TT * OO };
    const bool act[2] = { act0, act1 };

    // ---- per-batch state init ----
    #pragma unroll
    for (int lb = 0; lb < 2; ++lb) {
        for (int idx = gtid; idx < NN * VV; idx += GTHREADS)
            gs->Ms[lb][idx] = M_bias[idx];
        if (gtid < VV) gs->cat[lb][II + gtid] = r_bias[gtid];
        if (gtid >= 29 && gtid < 36) gs->cat[lb][gtid] = 0.0f;
        if (gtid < II) gs->cat[lb][gtid] = xb[lb][gtid];
        gs->wprev[lb][r0] = 0.0f; gs->wprev[lb][r1] = 0.0f;
    }
    gbar(group);

    for (int t = 0; t < TT; ++t) {
        // ---- B: controller for both batches (joint weight reads) ----
        {
            const float4* w0 = reinterpret_cast<const float4*>(sm + WCT_OFF + gtid * 36);
            const float4* w1 = reinterpret_cast<const float4*>(sm + WCT_OFF + (gtid + 64) * 36);
            const float4* c0 = reinterpret_cast<const float4*>(gs->cat[0]);
            const float4* c1 = reinterpret_cast<const float4*>(gs->cat[1]);
            const bool has1 = (gtid < 36);
            float a00 = sm[BC_OFF + gtid], a10 = a00;
            float a01 = has1 ? sm[BC_OFF + gtid + 64] : 0.0f, a11 = a01;
            #pragma unroll
            for (int k = 0; k < 9; ++k) {
                float4 cv0 = c0[k], cv1 = c1[k];
                float4 wv0 = w0[k];
                a00 = dot4(cv0, wv0, a00); a10 = dot4(cv1, wv0, a10);
                if (has1) {
                    float4 wv1 = w1[k];
                    a01 = dot4(cv0, wv1, a01); a11 = dot4(cv1, wv1, a11);
                }
            }
            gs->h[0][gtid] = tanhf(a00); gs->h[1][gtid] = tanhf(a10);
            if (has1) { gs->h[0][gtid + 64] = tanhf(a01); gs->h[1][gtid + 64] = tanhf(a11); }
        }
        gbar(group);

        // ---- C: head GEMM for both batches (joint weight reads) ----
        {
            const int o0 = gtid, o1 = gtid + 64;
            const bool has1 = (o1 < 92);
            const float4* w0 = reinterpret_cast<const float4*>(sm + WHT_OFF + o0 * 100);
            const float4* w1 = reinterpret_cast<const float4*>(sm + WHT_OFF + o1 * 100);
            const float4* h0 = reinterpret_cast<const float4*>(gs->h[0]);
            const float4* h1 = reinterpret_cast<const float4*>(gs->h[1]);
            float c00 = sm[BH_OFF + o0], c10 = c00;
            float c01 = has1 ? sm[BH_OFF + o1] : 0.0f, c11 = c01;
            #pragma unroll 5
            for (int k = 0; k < 25; ++k) {
                float4 hv0 = h0[k], hv1 = h1[k];
                float4 wv0 = w0[k];
                c00 = dot4(hv0, wv0, c00); c10 = dot4(hv1, wv0, c10);
                if (has1) {
                    float4 wv1 = w1[k];
                    c01 = dot4(hv0, wv1, c01); c11 = dot4(hv1, wv1, c11);
                }
            }
            head_dispatch(gs, 0, o0, c00); head_dispatch(gs, 1, o0, c10);
            if (has1) { head_dispatch(gs, 0, o1, c01); head_dispatch(gs, 1, o1, c11); }
        }
        gbar(group);

        // ==== per-batch phases D..J ====
        #pragma unroll 1
        for (int lb = 0; lb < 2; ++lb) {
            // ---- D: fused M pass (2 rows/thread, float4) + side jobs ----
            float dr0 = 0.0f, dw0 = 0.0f, ss0 = 0.0f;
            float dr1 = 0.0f, dw1 = 0.0f, ss1 = 0.0f;
            {
                const float4* M0 = reinterpret_cast<const float4*>(&gs->Ms[lb][r0 * VV]);
                const float4* M1 = reinterpret_cast<const float4*>(&gs->Ms[lb][r1 * VV]);
                const float4* kr4 = reinterpret_cast<const float4*>(gs->kr[lb]);
                const float4* kw4 = reinterpret_cast<const float4*>(gs->kw[lb]);
                #pragma unroll
                for (int v = 0; v < 5; ++v) {
                    float4 kvr = kr4[v], kvw = kw4[v];
                    float4 m0 = M0[v], m1 = M1[v];
                    dr0 = dot4(m0, kvr, dr0); dw0 = dot4(m0, kvw, dw0); ss0 = dot4(m0, m0, ss0);
                    dr1 = dot4(m1, kvr, dr1); dw1 = dot4(m1, kvw, dw1); ss1 = dot4(m1, m1, ss1);
                }
            }
            const float mn0 = sqrtf(ss0), mn1 = sqrtf(ss1);
            if (gtid == 40) {
                float a0 = gs->praw[lb][0], a1 = gs->praw[lb][1], a2 = gs->praw[lb][2];
                float m = fmaxf(a0, fmaxf(a1, a2));
                float e0 = __expf(a0 - m), e1 = __expf(a1 - m), e2 = __expf(a2 - m);
                float s = e0 + e1 + e2;
                gs->scal[lb][3] = e0 / s; gs->scal[lb][4] = e1 / s; gs->scal[lb][5] = e2 / s;
            } else if (gtid == 41) {
                float s2 = 0.0f;
                #pragma unroll
                for (int v = 0; v < VV; ++v) s2 = fmaf(gs->kr[lb][v], gs->kr[lb][v], s2);
                gs->knorm[lb][0] = sqrtf(s2);
            } else if (gtid == 42) {
                float a0 = gs->praw[lb][3], a1 = gs->praw[lb][4], a2 = gs->praw[lb][5];
                float m = fmaxf(a0, fmaxf(a1, a2));
                float e0 = __expf(a0 - m), e1 = __expf(a1 - m), e2 = __expf(a2 - m);
                float s = e0 + e1 + e2;
                gs->scal[lb][9] = e0 / s; gs->scal[lb][10] = e1 / s; gs->scal[lb][11] = e2 / s;
            } else if (gtid == 43) {
                float s2 = 0.0f;
                #pragma unroll
                for (int v = 0; v < VV; ++v) s2 = fmaf(gs->kw[lb][v], gs->kw[lb][v], s2);
                gs->knorm[lb][1] = sqrtf(s2);
            }
            gbar(group);

            // ---- E: dual-head content softmax ----
            const float g_r = gs->scal[lb][1], gamma_r = gs->scal[lb][2];
            const float s0r = gs->scal[lb][3], s1r = gs->scal[lb][4], s2r = gs->scal[lb][5];
            const float g_w = gs->scal[lb][7], gamma_w = gs->scal[lb][8];
            const float s0w = gs->scal[lb][9], s1w = gs->scal[lb][10], s2w = gs->scal[lb][11];
            const float beta_r = gs->scal[lb][0], beta_w = gs->scal[lb][6];
            const float knr = gs->knorm[lb][0], knw = gs->knorm[lb][1];
            float er0 = __expf(beta_r * __fdividef(dr0, fmaf(knr, mn0, EPSF)));
            float er1 = __expf(beta_r * __fdividef(dr1, fmaf(knr, mn1, EPSF)));
            float ew0 = __expf(beta_w * __fdividef(dw0, fmaf(knw, mn0, EPSF)));
            float ew1 = __expf(beta_w * __fdividef(dw1, fmaf(knw, mn1, EPSF)));
            float sr = er0 + er1, sw = ew0 + ew1;
            #pragma unroll
            for (int o = 16; o; o >>= 1) {
                sr += __shfl_xor_sync(0xffffffffu, sr, o);
                sw += __shfl_xor_sync(0xffffffffu, sw, o);
            }
            if (lane == 0) { gs->redA[gw] = sr; gs->redB[gw] = sw; }
            gbar(group);
            {
                float isr = __fdividef(1.0f, gs->redA[0] + gs->redA[1]);
                float isw = __fdividef(1.0f, gs->redB[0] + gs->redB[1]);
                float wcr0 = er0 * isr, wcr1 = er1 * isr;
                gs->wg[r0] = fmaf(g_r, wcr0 - gs->wprev[lb][r0], gs->wprev[lb][r0]);
                gs->wg[r1] = fmaf(g_r, wcr1 - gs->wprev[lb][r1], gs->wprev[lb][r1]);
                er0 = ew0 * isw; er1 = ew1 * isw;    // stash wcw0, wcw1
            }
            gbar(group);

            // ---- F: read-head shift + sharpen ----
            {
                float ws0 = s0r * gs->wg[(r0 + 1) & (NN - 1)] + s1r * gs->wg[r0]
                          + s2r * gs->wg[(r0 + NN - 1) & (NN - 1)];
                float ws1 = s0r * gs->wg[(r1 + 1) & (NN - 1)] + s1r * gs->wg[r1]
                          + s2r * gs->wg[(r1 + NN - 1) & (NN - 1)];
                float wp0 = (ws0 > 0.0f) ? ex2_(gamma_r * __log2f(ws0)) : 0.0f;
                float wp1 = (ws1 > 0.0f) ? ex2_(gamma_r * __log2f(ws1)) : 0.0f;
                float sp = wp0 + wp1;
                #pragma unroll
                for (int o = 16; o; o >>= 1) sp += __shfl_xor_sync(0xffffffffu, sp, o);
                if (lane == 0) gs->redA[gw] = sp;
                gbar(group);
                float isp = __fdividef(1.0f, gs->redA[0] + gs->redA[1] + EPSF);
                gs->wr[r0] = wp0 * isp;
                gs->wr[r1] = wp1 * isp;
            }
            gbar(group);

            // ---- G: write-head interpolation || r = wr @ M (60 thr) ----
            gs->wg[r0] = fmaf(g_w, er0 - gs->wr[r0], gs->wr[r0]);
            gs->wg[r1] = fmaf(g_w, er1 - gs->wr[r1], gs->wr[r1]);
            if (gtid < 60) {
                const int v = gtid % 20, q = gtid / 20;
                const int beg = q * 43, end = (q == 2) ? NN : beg + 43;
                float acc = 0.0f;
                for (int j = beg; j < end; ++j)
                    acc = fmaf(gs->wr[j], gs->Ms[lb][j * VV + v], acc);
                gs->part[q * 20 + v] = acc;
            }
            gbar(group);

            // ---- H: write-head shift + sharpen || r combine ----
            float wpw0, wpw1;
            {
                float ws0 = s0w * gs->wg[(r0 + 1) & (NN - 1)] + s1w * gs->wg[r0]
                          + s2w * gs->wg[(r0 + NN - 1) & (NN - 1)];
                float ws1 = s0w * gs->wg[(r1 + 1) & (NN - 1)] + s1w * gs->wg[r1]
                          + s2w * gs->wg[(r1 + NN - 1) & (NN - 1)];
                wpw0 = (ws0 > 0.0f) ? ex2_(gamma_w * __log2f(ws0)) : 0.0f;
                wpw1 = (ws1 > 0.0f) ? ex2_(gamma_w * __log2f(ws1)) : 0.0f;
                float sp = wpw0 + wpw1;
                #pragma unroll
                for (int o = 16; o; o >>= 1) sp += __shfl_xor_sync(0xffffffffu, sp, o);
                if (lane == 0) gs->redB[gw] = sp;
            }
            if (gtid < VV)
                gs->cat[lb][II + gtid] = gs->part[gtid] + gs->part[20 + gtid] + gs->part[40 + gtid];
            gbar(group);

            // ---- I: finalize ww + M update (float4) || output partials ----
            {
                float isp = __fdividef(1.0f, gs->redB[0] + gs->redB[1] + EPSF);
                float ww0 = wpw0 * isp, ww1 = wpw1 * isp;
                gs->wprev[lb][r0] = ww0; gs->wprev[lb][r1] = ww1;
                float4* M0 = reinterpret_cast<float4*>(&gs->Ms[lb][r0 * VV]);
                float4* M1 = reinterpret_cast<float4*>(&gs->Ms[lb][r1 * VV]);
                const float4* ev4 = reinterpret_cast<const float4*>(gs->ev[lb]);
                const float4* av4 = reinterpret_cast<const float4*>(gs->av[lb]);
                #pragma unroll
                for (int v = 0; v < 5; ++v) {
                    float4 e = ev4[v], a = av4[v];
                    float4 m0 = M0[v], m1 = M1[v];
                    m0.x = fmaf(ww0, a.x - e.x * m0.x, m0.x);
                    m0.y = fmaf(ww0, a.y - e.y * m0.y, m0.y);
                    m0.z = fmaf(ww0, a.z - e.z * m0.z, m0.z);
                    m0.w = fmaf(ww0, a.w - e.w * m0.w, m0.w);
                    m1.x = fmaf(ww1, a.x - e.x * m1.x, m1.x);
                    m1.y = fmaf(ww1, a.y - e.y * m1.y, m1.y);
                    m1.z = fmaf(ww1, a.z - e.z * m1.z, m1.z);
                    m1.w = fmaf(ww1, a.w - e.w * m1.w, m1.w);
                    M0[v] = m0; M1[v] = m1;
                }
            }
            {
                const int o = gtid & 7, seg = gtid >> 3;      // 8 segs of 15
                float acc = 0.0f;
                #pragma unroll
                for (int j = seg * 15; j < seg * 15 + 15; ++j) {
                    float v = (j < CC) ? gs->h[lb][j] : gs->cat[lb][II + (j - CC)];
                    acc = fmaf(v, Wfs[j * 8 + o], acc);
                }
                gs->part[gtid] = acc;
            }
            gbar(group);

            // ---- J: output store || prefetch x_{t+1} ----
            if (act[lb] && gtid < OO) {
                float s = bfs[gtid];
                #pragma unroll
                for (int q = 0; q < 8; ++q) s += gs->part[q * 8 + gtid];
                ob[lb][t * OO + gtid] = sigmoidf_(s);
            }
            if (gtid >= 40 && gtid < 40 + II && t + 1 < TT)
                gs->cat[lb][gtid - 40] = xb[lb][(t + 1) * II + (gtid - 40)];
            gbar(group);
        }
    }
}

extern "C" void kernel_launch(void* const* d_in, const int* in_sizes, int n_in,
                              void* d_out, int out_size) {
    const float* x      = (const float*)d_in[0];
    const float* Wc     = (const float*)d_in[1];
    const float* bc     = (const float*)d_in[2];
    const float* Wr     = (const float*)d_in[3];
    const float* br     = (const float*)d_in[4];
    const float* Ww     = (const float*)d_in[5];
    const float* bw     = (const float*)d_in[6];
    const float* Wf     = (const float*)d_in[7];
    const float* bf     = (const float*)d_in[8];
    const float* r_bias = (const float*)d_in[9];
    const float* M_bias = (const float*)d_in[10];
    float* out = (float*)d_out;

    const int Btot = in_sizes[0] / (TT * II);
    cudaFuncSetAttribute(ntm_kernel, cudaFuncAttributeMaxDynamicSharedMemorySize,
                         DYN_SMEM_BYTES);
    int grid = (Btot + NB_PER_CTA - 1) / NB_PER_CTA;   // 14 batches per CTA
    if (grid < 1) grid = 1;
    ntm_kernel<<<grid, 448, DYN_SMEM_BYTES>>>(x, Wc, bc, Wr, br, Ww, bw, Wf, bf,
                                              r_bias, M_bias, out, Btot);
}

// round 12
// speedup vs baseline: 2.3572x; 1.2611x over previous
#include <cuda_runtime.h>

// NTM forward: B=2048, T=64, I=9, N=128, V=20, S=3, C=100, O=8
#define TT 64
#define II 9
#define NN 128
#define VV 20
#define CC 100
#define OO 8
#define EPSF 1e-8f

#define NGROUPS 7
#define GTHREADS 64
#define NB_PER_CTA (NGROUPS * 2)

// smem weight layout (floats)
#define WCT_OFF 0            // 100 x 36 (Wc^T rows; cols 29..35 zero)
#define WHT_OFF 3600         // 92 x 100 (head rows: o<26 -> Wr col o, else Ww col o-26)
#define WF_OFF  12800        // 120 x 8
#define BC_OFF  13760        // 100
#define BH_OFF  13860        // 92 (br | bw)
#define BF_OFF  13952        // 8
#define GS_OFF  13960        // *4 % 16 == 0

struct GroupState {
    float Ms[2][NN * VV];       // 5120 (pitch 20; stride-32 row ownership -> conflict-free float4)
    float h[2][104];            // 208 (100 used, float4-aligned)
    float cat[2][36];           // 72  (x(9), r(20), zero pad)
    float kr[2][VV], kw[2][VV], ev[2][VV], av[2][VV];   // 160
    float wrS[2][NN];           // 256 (read weights, for the r-GEMM)
    float praw[2][6];           // 12
    float scal[2][12];          // 24
    float opart[2][32];         // 64
};                               // 5916 floats = 23664 B

#define DYN_SMEM_BYTES ((GS_OFF + NGROUPS * (int)(sizeof(GroupState) / 4)) * 4)

__device__ __forceinline__ float sigmoidf_(float x) {
    return 1.0f / (1.0f + __expf(-x));
}
__device__ __forceinline__ float softplusf_(float x) {
    return fmaxf(x, 0.0f) + log1pf(__expf(-fabsf(x)));
}
__device__ __forceinline__ float ex2_(float x) {
    float r;
    asm("ex2.approx.ftz.f32 %0, %1;" : "=f"(r) : "f"(x));
    return r;
}
__device__ __forceinline__ void gbar(int g) {   // 64-thread group barrier (ids 1..7)
    asm volatile("bar.sync %0, 64;" :: "r"(g + 1) : "memory");
}
__device__ __forceinline__ float dot4(const float4 a, const float4 b, float acc) {
    acc = fmaf(a.x, b.x, acc); acc = fmaf(a.y, b.y, acc);
    acc = fmaf(a.z, b.z, acc); acc = fmaf(a.w, b.w, acc);
    return acc;
}
__device__ __forceinline__ float wsum32(float v) {
    #pragma unroll
    for (int o = 16; o; o >>= 1) v += __shfl_xor_sync(0xffffffffu, v, o);
    return v;
}

__device__ __forceinline__ void head_dispatch(GroupState* G, int lb, int o, float v) {
    if (o < 20)       G->kr[lb][o] = tanhf(v);
    else if (o == 20) G->scal[lb][0] = softplusf_(v);
    else if (o == 21) G->scal[lb][1] = sigmoidf_(v);
    else if (o < 25)  G->praw[lb][o - 22] = v;
    else if (o == 25) G->scal[lb][2] = 1.0f + softplusf_(v);
    else if (o < 46)  G->kw[lb][o - 26] = tanhf(v);
    else if (o == 46) G->scal[lb][6] = softplusf_(v);
    else if (o == 47) G->scal[lb][7] = sigmoidf_(v);
    else if (o < 51)  G->praw[lb][3 + o - 48] = v;
    else if (o == 51) G->scal[lb][8] = 1.0f + softplusf_(v);
    else if (o < 72)  G->ev[lb][o - 52] = sigmoidf_(v);
    else              G->av[lb][o - 72] = tanhf(v);
}

// Circular shift: ws[n] = s0*w[n+1] + s1*w[n] + s2*w[n-1], rows n = lane + 32*j.
__device__ __forceinline__ void conv_shift(const float* w, float* ws, int lane,
                                           float s0, float s1, float s2) {
    float wm1[4], wp1[4], l31[4], l0[4];
    #pragma unroll
    for (int j = 0; j < 4; ++j) {
        wm1[j] = __shfl_sync(0xffffffffu, w[j], (lane + 31) & 31);
        wp1[j] = __shfl_sync(0xffffffffu, w[j], (lane + 1) & 31);
        l31[j] = __shfl_sync(0xffffffffu, w[j], 31);
        l0[j]  = __shfl_sync(0xffffffffu, w[j], 0);
    }
    if (lane == 0) {                 // row-1 of row 32j is lane31 slot (j+3)&3
        #pragma unroll
        for (int j = 0; j < 4; ++j) wm1[j] = l31[(j + 3) & 3];
    }
    if (lane == 31) {                // row+1 of row 31+32j is lane0 slot (j+1)&3
        #pragma unroll
        for (int j = 0; j < 4; ++j) wp1[j] = l0[(j + 1) & 3];
    }
    #pragma unroll
    for (int j = 0; j < 4; ++j)
        ws[j] = s0 * wp1[j] + s1 * w[j] + s2 * wm1[j];
}

__global__ __launch_bounds__(448, 1) void ntm_kernel(
    const float* __restrict__ x,
    const float* __restrict__ Wc, const float* __restrict__ bc,
    const float* __restrict__ Wr, const float* __restrict__ br,
    const float* __restrict__ Ww, const float* __restrict__ bw,
    const float* __restrict__ Wf, const float* __restrict__ bf,
    const float* __restrict__ r_bias, const float* __restrict__ M_bias,
    float* __restrict__ out, int Btot)
{
    extern __shared__ float sm[];
    const int tid = threadIdx.x;

    // ---- one-time transposed weight staging ----
    for (int i = tid; i < 3600; i += 448) sm[WCT_OFF + i] = 0.0f;
    __syncthreads();
    for (int i = tid; i < 2900; i += 448) {
        int r = i / 100, c = i % 100;
        sm[WCT_OFF + c * 36 + r] = Wc[i];
    }
    for (int i = tid; i < 2600; i += 448) {
        int c = i / 26, o = i % 26;
        sm[WHT_OFF + o * 100 + c] = Wr[i];
    }
    for (int i = tid; i < 6600; i += 448) {
        int c = i / 66, o = i % 66;
        sm[WHT_OFF + (26 + o) * 100 + c] = Ww[i];
    }
    for (int i = tid; i < 960;  i += 448) sm[WF_OFF + i] = Wf[i];
    for (int i = tid; i < 100;  i += 448) sm[BC_OFF + i] = bc[i];
    for (int i = tid; i < 26;   i += 448) sm[BH_OFF + i] = br[i];
    for (int i = tid; i < 66;   i += 448) sm[BH_OFF + 26 + i] = bw[i];
    for (int i = tid; i < 8;    i += 448) sm[BF_OFF + i] = bf[i];
    __syncthreads();

    const int group = tid >> 6;
    const int gtid = tid & 63;
    const int lane = tid & 31;
    const int gw = gtid >> 5;             // warp in group = batch owner
    GroupState* gs = reinterpret_cast<GroupState*>(sm + GS_OFF) + group;

    const float* Wfs = sm + WF_OFF;
    const float* bfs = sm + BF_OFF;

    const int base = (blockIdx.x * NGROUPS + group) * 2;
    const int b0e = (base < Btot) ? base : (Btot - 1);
    const int b1e = (base + 1 < Btot) ? (base + 1) : (Btot - 1);
    const float* xb[2] = { x + (size_t)b0e * TT * II, x + (size_t)b1e * TT * II };
    float* ob[2] = { out + (size_t)b0e * TT * OO, out + (size_t)b1e * TT * OO };
    const bool act[2] = { base < Btot, base + 1 < Btot };

    // ---- state init ----
    #pragma unroll
    for (int lb = 0; lb < 2; ++lb) {
        for (int idx = gtid; idx < NN * VV; idx += GTHREADS)
            gs->Ms[lb][idx] = M_bias[idx];
        if (gtid < VV) gs->cat[lb][II + gtid] = r_bias[gtid];
        if (gtid >= 29 && gtid < 36) gs->cat[lb][gtid] = 0.0f;
        if (gtid < II) gs->cat[lb][gtid] = xb[lb][gtid];
    }
    float wprev[4] = {0.0f, 0.0f, 0.0f, 0.0f};    // rows lane+32j of own batch
    gbar(group);

    for (int t = 0; t < TT; ++t) {
        // ---- B: controller for both batches (64 thr, joint weight reads) ----
        {
            const float4* w0 = reinterpret_cast<const float4*>(sm + WCT_OFF + gtid * 36);
            const float4* w1 = reinterpret_cast<const float4*>(sm + WCT_OFF + (gtid + 64) * 36);
            const float4* c0 = reinterpret_cast<const float4*>(gs->cat[0]);
            const float4* c1 = reinterpret_cast<const float4*>(gs->cat[1]);
            const bool has1 = (gtid < 36);
            float a00 = sm[BC_OFF + gtid], a10 = a00;
            float a01 = has1 ? sm[BC_OFF + gtid + 64] : 0.0f, a11 = a01;
            #pragma unroll
            for (int k = 0; k < 9; ++k) {
                float4 cv0 = c0[k], cv1 = c1[k];
                float4 wv0 = w0[k];
                a00 = dot4(cv0, wv0, a00); a10 = dot4(cv1, wv0, a10);
                if (has1) {
                    float4 wv1 = w1[k];
                    a01 = dot4(cv0, wv1, a01); a11 = dot4(cv1, wv1, a11);
                }
            }
            gs->h[0][gtid] = tanhf(a00); gs->h[1][gtid] = tanhf(a10);
            if (has1) { gs->h[0][gtid + 64] = tanhf(a01); gs->h[1][gtid + 64] = tanhf(a11); }
        }
        gbar(group);

        // ---- C: head GEMM for both batches (64 thr, joint weight reads) ----
        {
            const int o0 = gtid, o1 = gtid + 64;
            const bool has1 = (o1 < 92);
            const float4* w0 = reinterpret_cast<const float4*>(sm + WHT_OFF + o0 * 100);
            const float4* w1 = reinterpret_cast<const float4*>(sm + WHT_OFF + o1 * 100);
            const float4* h0 = reinterpret_cast<const float4*>(gs->h[0]);
            const float4* h1 = reinterpret_cast<const float4*>(gs->h[1]);
            float c00 = sm[BH_OFF + o0], c10 = c00;
            float c01 = has1 ? sm[BH_OFF + o1] : 0.0f, c11 = c01;
            #pragma unroll 5
            for (int k = 0; k < 25; ++k) {
                float4 hv0 = h0[k], hv1 = h1[k];
                float4 wv0 = w0[k];
                c00 = dot4(hv0, wv0, c00); c10 = dot4(hv1, wv0, c10);
                if (has1) {
                    float4 wv1 = w1[k];
                    c01 = dot4(hv0, wv1, c01); c11 = dot4(hv1, wv1, c11);
                }
            }
            head_dispatch(gs, 0, o0, c00); head_dispatch(gs, 1, o0, c10);
            if (has1) { head_dispatch(gs, 0, o1, c01); head_dispatch(gs, 1, o1, c11); }
        }
        gbar(group);

        // ==== warp-local D..J: warp gw owns batch lb = gw ====
        const int lb = gw;
        const float4* kr4 = reinterpret_cast<const float4*>(gs->kr[lb]);
        const float4* kw4 = reinterpret_cast<const float4*>(gs->kw[lb]);

        // key norms (redundant per lane; broadcast loads)
        float kk = 0.0f, kq = 0.0f;
        #pragma unroll
        for (int v = 0; v < 5; ++v) {
            float4 a = kr4[v], b = kw4[v];
            kk = dot4(a, a, kk); kq = dot4(b, b, kq);
        }
        const float knr = sqrtf(kk), knw = sqrtf(kq);

        // D: M pass, 4 rows/lane (rows lane+32j)
        float dr[4], dw[4], mn[4];
        #pragma unroll
        for (int j = 0; j < 4; ++j) {
            const float4* Mr = reinterpret_cast<const float4*>(&gs->Ms[lb][(lane + 32 * j) * VV]);
            float d1 = 0.0f, d2 = 0.0f, ss = 0.0f;
            #pragma unroll
            for (int v = 0; v < 5; ++v) {
                float4 kvr = kr4[v], kvw = kw4[v], m = Mr[v];
                d1 = dot4(m, kvr, d1); d2 = dot4(m, kvw, d2); ss = dot4(m, m, ss);
            }
            dr[j] = d1; dw[j] = d2; mn[j] = sqrtf(ss);
        }

        // shift softmaxes (redundant per lane)
        float s0r, s1r, s2r, s0w, s1w, s2w;
        {
            float a0 = gs->praw[lb][0], a1 = gs->praw[lb][1], a2 = gs->praw[lb][2];
            float m = fmaxf(a0, fmaxf(a1, a2));
            float e0 = __expf(a0 - m), e1 = __expf(a1 - m), e2 = __expf(a2 - m);
            float is = __fdividef(1.0f, e0 + e1 + e2);
            s0r = e0 * is; s1r = e1 * is; s2r = e2 * is;
            a0 = gs->praw[lb][3]; a1 = gs->praw[lb][4]; a2 = gs->praw[lb][5];
            m = fmaxf(a0, fmaxf(a1, a2));
            e0 = __expf(a0 - m); e1 = __expf(a1 - m); e2 = __expf(a2 - m);
            is = __fdividef(1.0f, e0 + e1 + e2);
            s0w = e0 * is; s1w = e1 * is; s2w = e2 * is;
        }
        const float beta_r = gs->scal[lb][0], g_r = gs->scal[lb][1], gamma_r = gs->scal[lb][2];
        const float beta_w = gs->scal[lb][6], g_w = gs->scal[lb][7], gamma_w = gs->scal[lb][8];

        // E: content softmax (warp-local)
        float er[4], ew[4], sr = 0.0f, sw = 0.0f;
        #pragma unroll
        for (int j = 0; j < 4; ++j) {
            er[j] = __expf(beta_r * __fdividef(dr[j], fmaf(knr, mn[j], EPSF)));
            ew[j] = __expf(beta_w * __fdividef(dw[j], fmaf(knw, mn[j], EPSF)));
            sr += er[j]; sw += ew[j];
        }
        sr = wsum32(sr); sw = wsum32(sw);
        const float isr = __fdividef(1.0f, sr), isw = __fdividef(1.0f, sw);
        float wg[4];
        #pragma unroll
        for (int j = 0; j < 4; ++j)
            wg[j] = fmaf(g_r, er[j] * isr - wprev[j], wprev[j]);

        // F: read-head shift + sharpen -> wr (regs + smem for r-GEMM)
        float wr_[4];
        {
            float ws[4];
            conv_shift(wg, ws, lane, s0r, s1r, s2r);
            float sp = 0.0f;
            #pragma unroll
            for (int j = 0; j < 4; ++j) {
                wr_[j] = (ws[j] > 0.0f) ? ex2_(gamma_r * __log2f(ws[j])) : 0.0f;
                sp += wr_[j];
            }
            sp = wsum32(sp);
            float isp = __fdividef(1.0f, sp + EPSF);
            #pragma unroll
            for (int j = 0; j < 4; ++j) {
                wr_[j] *= isp;
                gs->wrS[lb][lane + 32 * j] = wr_[j];
            }
        }

        // write-head interpolation + H shift + sharpen (registers only)
        float ww[4];
        {
            float wgw[4], ws[4];
            #pragma unroll
            for (int j = 0; j < 4; ++j)
                wgw[j] = fmaf(g_w, ew[j] * isw - wr_[j], wr_[j]);
            conv_shift(wgw, ws, lane, s0w, s1w, s2w);
            float sp = 0.0f;
            #pragma unroll
            for (int j = 0; j < 4; ++j) {
                ww[j] = (ws[j] > 0.0f) ? ex2_(gamma_w * __log2f(ws[j])) : 0.0f;
                sp += ww[j];
            }
            sp = wsum32(sp);
            float isp = __fdividef(1.0f, sp + EPSF);
            #pragma unroll
            for (int j = 0; j < 4; ++j) {
                ww[j] *= isp;
                wprev[j] = ww[j];
            }
        }
        __syncwarp();    // wrS visible to all lanes

        // G: r = wr @ M (lanes 0..19, v = lane), reads pre-update M
        if (lane < VV) {
            float acc = 0.0f;
            #pragma unroll 8
            for (int j = 0; j < NN; ++j)
                acc = fmaf(gs->wrS[lb][j], gs->Ms[lb][j * VV + lane], acc);
            gs->cat[lb][II + lane] = acc;
        }
        __syncwarp();    // M reads done; cat visible

        // I: M update, 4 rows/lane
        {
            const float4* ev4 = reinterpret_cast<const float4*>(gs->ev[lb]);
            const float4* av4 = reinterpret_cast<const float4*>(gs->av[lb]);
            #pragma unroll
            for (int j = 0; j < 4; ++j) {
                float4* Mr = reinterpret_cast<float4*>(&gs->Ms[lb][(lane + 32 * j) * VV]);
                float w = ww[j];
                #pragma unroll
                for (int v = 0; v < 5; ++v) {
                    float4 e = ev4[v], a = av4[v], m = Mr[v];
                    m.x = fmaf(w, a.x - e.x * m.x, m.x);
                    m.y = fmaf(w, a.y - e.y * m.y, m.y);
                    m.z = fmaf(w, a.z - e.z * m.z, m.z);
                    m.w = fmaf(w, a.w - e.w * m.w, m.w);
                    Mr[v] = m;
                }
            }
        }

        // output GEMM: 4 segs of 30 over [h, r]
        {
            const int o = lane & 7, seg = lane >> 3;
            float acc = 0.0f;
            #pragma unroll
            for (int jj = 0; jj < 30; ++jj) {
                int j = seg * 30 + jj;
                float v = (j < CC) ? gs->h[lb][j] : gs->cat[lb][II + (j - CC)];
                acc = fmaf(v, Wfs[j * 8 + o], acc);
            }
            gs->opart[lb][lane] = acc;
        }
        __syncwarp();
        if (act[lb] && lane < OO) {
            float s = bfs[lane] + gs->opart[lb][lane] + gs->opart[lb][lane + 8]
                    + gs->opart[lb][lane + 16] + gs->opart[lb][lane + 24];
            ob[lb][t * OO + lane] = sigmoidf_(s);
        }
        if (lane >= 8 && lane < 8 + II && t + 1 < TT)
            gs->cat[lb][lane - 8] = xb[lb][(t + 1) * II + (lane - 8)];
        gbar(group);   // step boundary: both batches' h/cat ready for next B
    }
}

extern "C" void kernel_launch(void* const* d_in, const int* in_sizes, int n_in,
                              void* d_out, int out_size) {
    const float* x      = (const float*)d_in[0];
    const float* Wc     = (const float*)d_in[1];
    const float* bc     = (const float*)d_in[2];
    const float* Wr     = (const float*)d_in[3];
    const float* br     = (const float*)d_in[4];
    const float* Ww     = (const float*)d_in[5];
    const float* bw     = (const float*)d_in[6];
    const float* Wf     = (const float*)d_in[7];
    const float* bf     = (const float*)d_in[8];
    const float* r_bias = (const float*)d_in[9];
    const float* M_bias = (const float*)d_in[10];
    float* out = (float*)d_out;

    const int Btot = in_sizes[0] / (TT * II);
    cudaFuncSetAttribute(ntm_kernel, cudaFuncAttributeMaxDynamicSharedMemorySize,
                         DYN_SMEM_BYTES);
    int grid = (Btot + NB_PER_CTA - 1) / NB_PER_CTA;
    if (grid < 1) grid = 1;
    ntm_kernel<<<grid, 448, DYN_SMEM_BYTES>>>(x, Wc, bc, Wr, br, Ww, bw, Wf, bf,
                                              r_bias, M_bias, out, Btot);
}